// round 2
// baseline (speedup 1.0000x reference)
#include <cuda_runtime.h>
#include <math.h>

#define Nn   8
#define Cc   64
#define Hh   96
#define Ww   96
#define COo  64
#define KKt  9
#define HW   (Hh*Ww)

// Transposed weights (device scratch; no allocs allowed)
__device__ float g_wT[KKt*Cc*COo];    // [kk][c][co]
__device__ float g_woffT[KKt*Cc*32];  // [kk][c][g*8+j], oc = g*7+j, zero-padded

__global__ void prep_weights(const float* __restrict__ w,
                             const float* __restrict__ w_off) {
    int i = blockIdx.x*blockDim.x + threadIdx.x;
    int stride = gridDim.x*blockDim.x;
    for (int idx = i; idx < KKt*Cc*COo; idx += stride) {
        int kk = idx / (Cc*COo);
        int r  = idx % (Cc*COo);
        int c  = r >> 6, co = r & 63;
        g_wT[idx] = w[(co*Cc + c)*KKt + kk];
    }
    for (int idx = i; idx < KKt*Cc*32; idx += stride) {
        int kk = idx / (Cc*32);
        int r  = idx % (Cc*32);
        int c  = r >> 5, slot = r & 31;
        int g = slot >> 3, j = slot & 7;
        int oc = g*7 + j;
        float v = 0.f;
        if (j < 7 && oc < 27) v = w_off[(oc*Cc + c)*KKt + kk];
        g_woffT[idx] = v;
    }
}

// Fused: offset conv (27ch) -> sigmoid/bilinear precompute -> deform conv GEMM.
// Block: 256 threads = 64 pixels (32x2 tile) x 4 groups. Grid: (144, 8).
__global__ __launch_bounds__(256) void fused_dcn(
    const float* __restrict__ x, const float* __restrict__ b_off,
    const float* __restrict__ bias, float* __restrict__ out)
{
    __shared__ __align__(16) float s_patch[64*64]; // [c][p]; aliased as s_off[p][28]
    __shared__ __align__(16) float s_w[64*64];     // weight chunk [c][co] / [c][32]
    __shared__ __align__(16) float s_bil[576*6];   // per (p,kk): w00..w11, baseIdx, steps

    const int tid = threadIdx.x;
    const int p   = tid & 63;
    const int g   = tid >> 6;
    const int n   = blockIdx.y;
    const int txi = blockIdx.x % 3;
    const int tyi = blockIdx.x / 3;
    const int pw  = txi*32 + (p & 31);
    const int ph  = tyi*2  + (p >> 5);

    const float* __restrict__ xn = x + n*Cc*HW;

    // ---------------- Phase 1: offset conv (27 out channels) ----------------
    float acc1[8];
    #pragma unroll
    for (int j = 0; j < 8; j++) acc1[j] = 0.f;

    for (int kk = 0; kk < 9; kk++) {
        const int ky = kk/3 - 1, kx = kk%3 - 1;
        __syncthreads();
        // gather integer-tap patch [c][p] (zero pad)
        {
            int yy = ph + ky, xx = pw + kx;
            bool ok = (yy >= 0) & (yy < Hh) & (xx >= 0) & (xx < Ww);
            int sidx = ok ? (yy*Ww + xx) : 0;
            #pragma unroll
            for (int i = 0; i < 16; i++) {
                int c = g*16 + i;
                float v = ok ? __ldg(xn + c*HW + sidx) : 0.f;
                s_patch[c*64 + p] = v;
            }
        }
        // load offset-weight chunk [c][32] (2048 floats, coalesced)
        {
            const float* src = g_woffT + kk*Cc*32;
            #pragma unroll
            for (int i = 0; i < 8; i++) s_w[tid + i*256] = src[tid + i*256];
        }
        __syncthreads();
        // GEMM: 27(+pad) channels, group g owns oc = g*7 .. g*7+6
        #pragma unroll 8
        for (int c = 0; c < 64; c++) {
            float xv = s_patch[c*64 + p];
            const float4* wr = (const float4*)(s_w + c*32 + g*8);
            float4 w0 = wr[0], w1 = wr[1];
            acc1[0] = fmaf(xv, w0.x, acc1[0]);
            acc1[1] = fmaf(xv, w0.y, acc1[1]);
            acc1[2] = fmaf(xv, w0.z, acc1[2]);
            acc1[3] = fmaf(xv, w0.w, acc1[3]);
            acc1[4] = fmaf(xv, w1.x, acc1[4]);
            acc1[5] = fmaf(xv, w1.y, acc1[5]);
            acc1[6] = fmaf(xv, w1.z, acc1[6]);
            acc1[7] = fmaf(xv, w1.w, acc1[7]);
        }
    }

    __syncthreads();
    // stash conv result as s_off[p][28] (aliases s_patch)
    {
        float* s_off = s_patch;
        int nj = (g < 3) ? 7 : 6;
        for (int j = 0; j < nj; j++) {
            int oc = g*7 + j;
            s_off[p*28 + oc] = acc1[j] + __ldg(b_off + oc);
        }
    }
    __syncthreads();

    // ---------------- Phase 2: bilinear/mask precompute ----------------
    {
        const float* s_off = s_patch;
        for (int i = tid; i < 576; i += 256) {
            int pp = i / 9, kk = i % 9;
            int ky = kk / 3, kx = kk % 3;
            int iph = tyi*2  + (pp >> 5);
            int ipw = txi*32 + (pp & 31);
            float dy = s_off[pp*28 + 2*kk];
            float dx = s_off[pp*28 + 2*kk + 1];
            float m  = s_off[pp*28 + 18 + kk];
            float sig = 1.f / (1.f + __expf(-m));
            float py = dy + (float)(ky + iph - 1);
            float px = dx + (float)(kx + ipw - 1);
            float y0f = floorf(py), x0f = floorf(px);
            float ly = py - y0f, lx = px - x0f;
            int y0 = (int)y0f, x0 = (int)x0f;
            int y1 = y0 + 1,   x1 = x0 + 1;
            float vy0 = (y0 >= 0 && y0 < Hh) ? 1.f : 0.f;
            float vy1 = (y1 >= 0 && y1 < Hh) ? 1.f : 0.f;
            float vx0 = (x0 >= 0 && x0 < Ww) ? 1.f : 0.f;
            float vx1 = (x1 >= 0 && x1 < Ww) ? 1.f : 0.f;
            float w00 = (1.f-ly)*(1.f-lx)*sig*vy0*vx0;
            float w01 = (1.f-ly)*lx      *sig*vy0*vx1;
            float w10 = ly      *(1.f-lx)*sig*vy1*vx0;
            float w11 = ly      *lx      *sig*vy1*vx1;
            int y0c = min(max(y0, 0), Hh-1);
            int x0c = min(max(x0, 0), Ww-1);
            int y1c = min(max(y1, 0), Hh-1);
            int x1c = min(max(x1, 0), Ww-1);
            int sy = (y1c - y0c) * Ww;   // 0 or 96
            int sx = (x1c - x0c);        // 0 or 1
            float* d = s_bil + i*6;
            d[0] = w00; d[1] = w01; d[2] = w10; d[3] = w11;
            ((int*)d)[4] = y0c*Ww + x0c;
            ((int*)d)[5] = sy | (sx << 12);
        }
    }

    // ---------------- Phase 3: deformable gather + main GEMM ----------------
    float acc[16];
    #pragma unroll
    for (int j = 0; j < 16; j++) acc[j] = 0.f;

    for (int kk = 0; kk < 9; kk++) {
        __syncthreads();
        // load main weight chunk [c][co] (4096 floats, coalesced)
        {
            const float* src = g_wT + kk*Cc*COo;
            #pragma unroll
            for (int i = 0; i < 16; i++) s_w[tid + i*256] = src[tid + i*256];
        }
        // gather bilinear samples into s_patch[c][p]
        {
            const float* d = s_bil + (p*9 + kk)*6;
            float w00 = d[0], w01 = d[1], w10 = d[2], w11 = d[3];
            int base = ((const int*)d)[4];
            int st   = ((const int*)d)[5];
            int sy = st & 0xFFF, sx = st >> 12;
            int i00 = base, i01 = base + sx, i10 = base + sy, i11 = base + sy + sx;
            #pragma unroll
            for (int i = 0; i < 16; i++) {
                int c = g*16 + i;
                const float* xc = xn + c*HW;
                float v = w00*__ldg(xc + i00) + w01*__ldg(xc + i01)
                        + w10*__ldg(xc + i10) + w11*__ldg(xc + i11);
                s_patch[c*64 + p] = v;
            }
        }
        __syncthreads();
        // GEMM: group g owns co = g*16 .. g*16+15
        #pragma unroll 4
        for (int c = 0; c < 64; c++) {
            float xv = s_patch[c*64 + p];
            const float4* wr = (const float4*)(s_w + c*64 + g*16);
            float4 a = wr[0], b = wr[1], cc = wr[2], dd = wr[3];
            acc[ 0] = fmaf(xv, a.x,  acc[ 0]);
            acc[ 1] = fmaf(xv, a.y,  acc[ 1]);
            acc[ 2] = fmaf(xv, a.z,  acc[ 2]);
            acc[ 3] = fmaf(xv, a.w,  acc[ 3]);
            acc[ 4] = fmaf(xv, b.x,  acc[ 4]);
            acc[ 5] = fmaf(xv, b.y,  acc[ 5]);
            acc[ 6] = fmaf(xv, b.z,  acc[ 6]);
            acc[ 7] = fmaf(xv, b.w,  acc[ 7]);
            acc[ 8] = fmaf(xv, cc.x, acc[ 8]);
            acc[ 9] = fmaf(xv, cc.y, acc[ 9]);
            acc[10] = fmaf(xv, cc.z, acc[10]);
            acc[11] = fmaf(xv, cc.w, acc[11]);
            acc[12] = fmaf(xv, dd.x, acc[12]);
            acc[13] = fmaf(xv, dd.y, acc[13]);
            acc[14] = fmaf(xv, dd.z, acc[14]);
            acc[15] = fmaf(xv, dd.w, acc[15]);
        }
    }

    // ---------------- epilogue ----------------
    #pragma unroll
    for (int j = 0; j < 16; j++) {
        int co = g*16 + j;
        out[((n*COo + co)*Hh + ph)*Ww + pw] = acc[j] + __ldg(bias + co);
    }
}

extern "C" void kernel_launch(void* const* d_in, const int* in_sizes, int n_in,
                              void* d_out, int out_size) {
    const float* x      = (const float*)d_in[0];
    const float* w_off  = (const float*)d_in[1];
    const float* b_off  = (const float*)d_in[2];
    const float* weight = (const float*)d_in[3];
    const float* bias   = (const float*)d_in[4];
    float* out = (float*)d_out;

    prep_weights<<<64, 256>>>(weight, w_off);
    dim3 grid(144, 8);
    fused_dcn<<<grid, 256>>>(x, b_off, bias, out);
}

// round 8
// speedup vs baseline: 1.3563x; 1.3563x over previous
#include <cuda_runtime.h>
#include <math.h>

#define Nn   8
#define Cc   64
#define Hh   96
#define Ww   96
#define COo  64
#define KKt  9
#define HW   (Hh*Ww)

typedef unsigned long long ull;

__device__ __forceinline__ ull ffma2(ull a, ull b, ull c) {
    ull d;
    asm("fma.rn.f32x2 %0, %1, %2, %3;" : "=l"(d) : "l"(a), "l"(b), "l"(c));
    return d;
}
__device__ __forceinline__ ull pack2(float x, float y) {
    ull d; asm("mov.b64 %0, {%1, %2};" : "=l"(d) : "f"(x), "f"(y)); return d;
}
__device__ __forceinline__ float2 unpack2(ull v) {
    float2 r; asm("mov.b64 {%0, %1}, %2;" : "=f"(r.x), "=f"(r.y) : "l"(v)); return r;
}

// Transposed weights (device scratch; no allocs allowed)
__device__ float g_wT[KKt*Cc*COo];    // [kk][c][co]      (co-pairs natural)
__device__ float g_woffT[KKt*Cc*32];  // [kk][c][slot=co], co<27 valid, else 0

__global__ void prep_weights(const float* __restrict__ w,
                             const float* __restrict__ w_off) {
    int i = blockIdx.x*blockDim.x + threadIdx.x;
    int stride = gridDim.x*blockDim.x;
    for (int idx = i; idx < KKt*Cc*COo; idx += stride) {
        int kk = idx / (Cc*COo);
        int r  = idx % (Cc*COo);
        int c  = r >> 6, co = r & 63;
        g_wT[idx] = w[(co*Cc + c)*KKt + kk];
    }
    for (int idx = i; idx < KKt*Cc*32; idx += stride) {
        int kk = idx / (Cc*32);
        int r  = idx % (Cc*32);
        int c  = r >> 5, slot = r & 31;
        float v = 0.f;
        if (slot < 27) v = w_off[(slot*Cc + c)*KKt + kk];
        g_woffT[idx] = v;
    }
}

// Fused: offset conv -> bilinear precompute -> deform conv GEMM, f32x2 math.
// Block: 128 threads = 32 px-pairs (64 px, 32x2 tile) x 4 groups. Grid: (144, 8).
__global__ __launch_bounds__(128) void fused_dcn(
    const float* __restrict__ x, const float* __restrict__ b_off,
    const float* __restrict__ bias, float* __restrict__ out)
{
    __shared__ __align__(16) float s_patch[64*64]; // [c][p]; aliased as s_off[p][28]
    __shared__ __align__(16) float s_w[64*64];     // weight chunk [c][co] / [c][32]
    __shared__ __align__(16) float s_bil[64*9*6];  // per (p,kk): w00..w11, baseIdx, steps

    const int tid = threadIdx.x;
    const int q   = tid & 31;       // pixel-pair index: pixels 2q, 2q+1
    const int g   = tid >> 5;       // group 0..3 (c-chunk for gather, co-chunk for GEMM)
    const int n   = blockIdx.y;
    const int txi = blockIdx.x % 3;
    const int tyi = blockIdx.x / 3;
    const int p0  = 2*q;
    const int pw0 = txi*32 + (p0 & 31);   // even; pair is (pw0, pw0+1) same row
    const int ph  = tyi*2  + (p0 >> 5);

    const float* __restrict__ xn = x + n*Cc*HW;

    // ---------------- Phase 1: offset conv (27 out ch, padded to 32) ----------------
    // thread: 2 px x 8 co (co = 8g..8g+7) as 4 co-pairs per px
    ull acc1[2][4];
    #pragma unroll
    for (int i = 0; i < 2; i++)
        #pragma unroll
        for (int j = 0; j < 4; j++) acc1[i][j] = 0ull;

    for (int kk = 0; kk < 9; kk++) {
        const int ky = kk/3 - 1, kx = kk%3 - 1;
        __syncthreads();
        // integer-tap patch gather: c-chunk 16, 2 px each (zero pad)
        {
            int yy = ph + ky;
            int xx0 = pw0 + kx, xx1 = xx0 + 1;
            bool oky = (yy >= 0) & (yy < Hh);
            bool ok0 = oky & (xx0 >= 0) & (xx0 < Ww);
            bool ok1 = oky & (xx1 >= 0) & (xx1 < Ww);
            int base = yy*Ww;
            #pragma unroll
            for (int i = 0; i < 16; i++) {
                int c = g*16 + i;
                const float* xc = xn + c*HW;
                float v0 = ok0 ? __ldg(xc + base + xx0) : 0.f;
                float v1 = ok1 ? __ldg(xc + base + xx1) : 0.f;
                *(float2*)(s_patch + c*64 + p0) = make_float2(v0, v1);
            }
        }
        // offset-weight chunk [c][32] : 2048 floats, 4 float4 per thread
        {
            const float4* src = (const float4*)(g_woffT + kk*Cc*32);
            float4* dst = (float4*)s_w;
            #pragma unroll
            for (int i = 0; i < 4; i++) dst[tid + i*128] = src[tid + i*128];
        }
        __syncthreads();
        #pragma unroll 4
        for (int c = 0; c < 64; c++) {
            float2 xv = *(const float2*)(s_patch + c*64 + p0);
            ull xa = pack2(xv.x, xv.x);
            ull xb = pack2(xv.y, xv.y);
            const ulonglong2* wr = (const ulonglong2*)(s_w + c*32 + g*8);
            #pragma unroll
            for (int m = 0; m < 2; m++) {
                ulonglong2 wp = wr[m];
                acc1[0][2*m  ] = ffma2(xa, wp.x, acc1[0][2*m  ]);
                acc1[0][2*m+1] = ffma2(xa, wp.y, acc1[0][2*m+1]);
                acc1[1][2*m  ] = ffma2(xb, wp.x, acc1[1][2*m  ]);
                acc1[1][2*m+1] = ffma2(xb, wp.y, acc1[1][2*m+1]);
            }
        }
    }

    __syncthreads();
    // stash conv result as s_off[p][28] (aliases s_patch)
    {
        float* s_off = s_patch;
        #pragma unroll
        for (int j = 0; j < 4; j++) {
            int co0 = g*8 + 2*j, co1 = co0 + 1;
            float2 v0 = unpack2(acc1[0][j]);  // px p0:   (co0, co1)
            float2 v1 = unpack2(acc1[1][j]);  // px p0+1: (co0, co1)
            if (co0 < 27) {
                float b = __ldg(b_off + co0);
                s_off[p0*28 + co0]     = v0.x + b;
                s_off[(p0+1)*28 + co0] = v1.x + b;
            }
            if (co1 < 27) {
                float b = __ldg(b_off + co1);
                s_off[p0*28 + co1]     = v0.y + b;
                s_off[(p0+1)*28 + co1] = v1.y + b;
            }
        }
    }
    __syncthreads();

    // ---------------- Phase 2: bilinear/mask precompute ----------------
    {
        const float* s_off = s_patch;
        for (int i = tid; i < 576; i += 128) {
            int pp = i / 9, kk = i % 9;
            int ky = kk / 3, kx = kk % 3;
            int iph = tyi*2  + (pp >> 5);
            int ipw = txi*32 + (pp & 31);
            float dy = s_off[pp*28 + 2*kk];
            float dx = s_off[pp*28 + 2*kk + 1];
            float m  = s_off[pp*28 + 18 + kk];
            float sig = 1.f / (1.f + __expf(-m));
            float py = dy + (float)(ky + iph - 1);
            float px = dx + (float)(kx + ipw - 1);
            float y0f = floorf(py), x0f = floorf(px);
            float ly = py - y0f, lx = px - x0f;
            int y0 = (int)y0f, x0 = (int)x0f;
            int y1 = y0 + 1,   x1 = x0 + 1;
            float vy0 = (y0 >= 0 && y0 < Hh) ? 1.f : 0.f;
            float vy1 = (y1 >= 0 && y1 < Hh) ? 1.f : 0.f;
            float vx0 = (x0 >= 0 && x0 < Ww) ? 1.f : 0.f;
            float vx1 = (x1 >= 0 && x1 < Ww) ? 1.f : 0.f;
            float w00 = (1.f-ly)*(1.f-lx)*sig*vy0*vx0;
            float w01 = (1.f-ly)*lx      *sig*vy0*vx1;
            float w10 = ly      *(1.f-lx)*sig*vy1*vx0;
            float w11 = ly      *lx      *sig*vy1*vx1;
            int y0c = min(max(y0, 0), Hh-1);
            int x0c = min(max(x0, 0), Ww-1);
            int y1c = min(max(y1, 0), Hh-1);
            int x1c = min(max(x1, 0), Ww-1);
            int sy = (y1c - y0c) * Ww;   // 0 or 96
            int sx = (x1c - x0c);        // 0 or 1
            float* d = s_bil + i*6;
            d[0] = w00; d[1] = w01; d[2] = w10; d[3] = w11;
            ((int*)d)[4] = y0c*Ww + x0c;
            ((int*)d)[5] = sy | (sx << 12);
        }
    }

    // ---------------- Phase 3: deformable gather + main GEMM ----------------
    // thread: 2 px x 16 co (co = 16g..16g+15) as 8 co-pairs per px
    ull acc[2][8];
    #pragma unroll
    for (int i = 0; i < 2; i++)
        #pragma unroll
        for (int j = 0; j < 8; j++) acc[i][j] = 0ull;

    for (int kk = 0; kk < 9; kk++) {
        __syncthreads();
        // main weight chunk [c][co]: 4096 floats, 8 float4 per thread
        {
            const float4* src = (const float4*)(g_wT + kk*Cc*COo);
            float4* dst = (float4*)s_w;
            #pragma unroll
            for (int i = 0; i < 8; i++) dst[tid + i*128] = src[tid + i*128];
        }
        // bilinear gather: c-chunk 16, 2 px each
        {
            const float* d0 = s_bil + (p0*9 + kk)*6;
            const float* d1 = s_bil + ((p0+1)*9 + kk)*6;
            float a00 = d0[0], a01 = d0[1], a10 = d0[2], a11 = d0[3];
            int baseA = ((const int*)d0)[4];
            int stA   = ((const int*)d0)[5];
            int syA = stA & 0xFFF, sxA = stA >> 12;
            int iA0 = baseA, iA1 = baseA + sxA, iA2 = baseA + syA, iA3 = baseA + syA + sxA;
            float b00 = d1[0], b01 = d1[1], b10 = d1[2], b11 = d1[3];
            int baseB = ((const int*)d1)[4];
            int stB   = ((const int*)d1)[5];
            int syB = stB & 0xFFF, sxB = stB >> 12;
            int iB0 = baseB, iB1 = baseB + sxB, iB2 = baseB + syB, iB3 = baseB + syB + sxB;
            #pragma unroll
            for (int i = 0; i < 16; i++) {
                int c = g*16 + i;
                const float* xc = xn + c*HW;
                float va = a00*__ldg(xc + iA0) + a01*__ldg(xc + iA1)
                         + a10*__ldg(xc + iA2) + a11*__ldg(xc + iA3);
                float vb = b00*__ldg(xc + iB0) + b01*__ldg(xc + iB1)
                         + b10*__ldg(xc + iB2) + b11*__ldg(xc + iB3);
                *(float2*)(s_patch + c*64 + p0) = make_float2(va, vb);
            }
        }
        __syncthreads();
        #pragma unroll 4
        for (int c = 0; c < 64; c++) {
            float2 xv = *(const float2*)(s_patch + c*64 + p0);
            ull xa = pack2(xv.x, xv.x);
            ull xb = pack2(xv.y, xv.y);
            const ulonglong2* wr = (const ulonglong2*)(s_w + c*64 + g*16);
            #pragma unroll
            for (int m = 0; m < 4; m++) {
                ulonglong2 wp = wr[m];
                acc[0][2*m  ] = ffma2(xa, wp.x, acc[0][2*m  ]);
                acc[0][2*m+1] = ffma2(xa, wp.y, acc[0][2*m+1]);
                acc[1][2*m  ] = ffma2(xb, wp.x, acc[1][2*m  ]);
                acc[1][2*m+1] = ffma2(xb, wp.y, acc[1][2*m+1]);
            }
        }
    }

    // ---------------- epilogue ----------------
    #pragma unroll
    for (int j = 0; j < 8; j++) {
        int co0 = g*16 + 2*j, co1 = co0 + 1;
        float2 a0 = unpack2(acc[0][j]);   // px p0:   (co0, co1)
        float2 a1 = unpack2(acc[1][j]);   // px p0+1: (co0, co1)
        float bb0 = __ldg(bias + co0);
        float bb1 = __ldg(bias + co1);
        *(float2*)(out + ((n*COo + co0)*Hh + ph)*Ww + pw0) = make_float2(a0.x + bb0, a1.x + bb0);
        *(float2*)(out + ((n*COo + co1)*Hh + ph)*Ww + pw0) = make_float2(a0.y + bb1, a1.y + bb1);
    }
}

extern "C" void kernel_launch(void* const* d_in, const int* in_sizes, int n_in,
                              void* d_out, int out_size) {
    const float* x      = (const float*)d_in[0];
    const float* w_off  = (const float*)d_in[1];
    const float* b_off  = (const float*)d_in[2];
    const float* weight = (const float*)d_in[3];
    const float* bias   = (const float*)d_in[4];
    float* out = (float*)d_out;

    prep_weights<<<64, 256>>>(weight, w_off);
    dim3 grid(144, 8);
    fused_dcn<<<grid, 128>>>(x, b_off, bias, out);
}